// round 11
// baseline (speedup 1.0000x reference)
#include <cuda_runtime.h>

#define N_ROWS 2048      // 256 * 8 tiles
#define L 128
#define OUT 65
#define OUT2 (OUT * OUT) // 4225
#define WPB 4            // independent warps per block, one tile each
#define EPS 1e-6f

__global__ __launch_bounds__(32 * WPB) void gasf_kernel(const float* __restrict__ x,
                                                        float* __restrict__ out) {
    // per-warp interleaved (c,s) arrays; cs_odd is shifted by one position so
    // any phase m in {0,1,2,3} has a 16B-aligned float4 view of (c,s)[m+4q ..]
    __shared__ __align__(16) float2 cs_even[WPB][68];   // (c,s)[0..64]
    __shared__ __align__(16) float2 cs_odd[WPB][68];    // (c,s)[1..64]

    const int lane = threadIdx.x & 31;
    const int w = threadIdx.x >> 5;
    const int T = blockIdx.x * WPB + w;        // tile id = input row
    const float POS_INF = __int_as_float(0x7f800000);

    // ---- preamble (R7-proven): compute c,s for positions 0..64 ----
    {
        float4 v = ((const float4*)(x + T * L))[lane];
        int nib = (v.x != 0.0f ? 1 : 0) | (v.y != 0.0f ? 2 : 0) |
                  (v.z != 0.0f ? 4 : 0) | (v.w != 0.0f ? 8 : 0);
        unsigned m = __ballot_sync(0xffffffffu, nib != 0);
        int first = L, last = -1;
        {
            int lf = __ffs(m) - 1;
            int ll = 31 - __clz(m | 1u);
            int nf = __shfl_sync(0xffffffffu, nib, m ? lf : 0);
            int nl = __shfl_sync(0xffffffffu, nib, m ? ll : 0);
            if (m) {
                first = 4 * lf + (__ffs(nf) - 1);
                last  = 4 * ll + (31 - __clz((unsigned)nl));
            }
        }
        const int p0 = 4 * lane;
        bool val0 = (p0 + 0 >= first) && (p0 + 0 <= last);
        bool val1 = (p0 + 1 >= first) && (p0 + 1 <= last);
        bool val2 = (p0 + 2 >= first) && (p0 + 2 <= last);
        bool val3 = (p0 + 3 >= first) && (p0 + 3 <= last);
        float mn = POS_INF, mx = -POS_INF;
        if (val0) { mn = fminf(mn, v.x); mx = fmaxf(mx, v.x); }
        if (val1) { mn = fminf(mn, v.y); mx = fmaxf(mx, v.y); }
        if (val2) { mn = fminf(mn, v.z); mx = fmaxf(mx, v.z); }
        if (val3) { mn = fminf(mn, v.w); mx = fmaxf(mx, v.w); }
        #pragma unroll
        for (int off = 16; off; off >>= 1) {
            mn = fminf(mn, __shfl_xor_sync(0xffffffffu, mn, off));
            mx = fmaxf(mx, __shfl_xor_sync(0xffffffffu, mx, off));
        }
        float xmin = fminf(mn, 0.0f);
        float xmax = fmaxf(mx, 0.0f);
        float inv_range = 2.0f / fmaxf(xmax - xmin, EPS);

        if (p0 < OUT) {
            float vv[4] = { v.x, v.y, v.z, v.w };
            bool vf[4] = { val0, val1, val2, val3 };
            #pragma unroll
            for (int k = 0; k < 4; ++k) {
                int p = p0 + k;
                if (p < OUT) {
                    float xn = vf[k] ? ((vv[k] - xmin) * inv_range - 1.0f) : 0.0f;
                    float c = fminf(fmaxf(xn, -1.0f + EPS), 1.0f - EPS);
                    float s = sqrtf(fmaxf(1.0f - c * c, 0.0f));
                    cs_even[w][p] = make_float2(c, s);
                    if (p >= 1) cs_odd[w][p - 1] = make_float2(c, s);
                }
            }
        }
    }
    __syncwarp();

    const float2* ce = cs_even[w];
    const float2* co = cs_odd[w];
    float* ob = out + (size_t)T * OUT2;

    const int half = lane >> 4;        // 0: row i, 1: row i+4 (same phase)
    const int q = lane & 15;           // quad index within the row

    // ---- main: rows 0..63 as (i, i+4) pairs, plus row 64 half-iter ----
    #pragma unroll
    for (int it = 0; it < 33; ++it) {
        const int i_lo = (it < 32) ? (8 * (it >> 2) + (it & 3)) : 64;
        const int m = (4 - ((i_lo + T) & 3)) & 3;         // alignment phase
        const int Q = (m < 2) ? 16 : 15;                  // aligned quads this row
        const int i = i_lo + ((it < 32) ? 4 * half : 0);
        const bool active = (q < Q) && ((it < 32) || (half == 0));
        if (active) {
            // (c,s)[j..j+3], j = m+4q, via phase-shifted 16B-aligned loads
            const float4* src = (const float4*)((m & 1) ? co : ce) + (m >> 1) + 2 * q;
            float4 p01 = src[0];                          // LDS.128 (deduped halves)
            float4 p23 = src[1];
            float2 a = ce[i];                             // LDS.64, 2 addrs/warp
            float4 r;
            r.x = fmaf(a.x, p01.x, -a.y * p01.y);
            r.y = fmaf(a.x, p01.z, -a.y * p01.w);
            r.z = fmaf(a.x, p23.x, -a.y * p23.y);
            r.w = fmaf(a.x, p23.z, -a.y * p23.w);
            *(float4*)(ob + i * OUT + m + 4 * q) = r;     // STG.128, 16B-aligned
        }
    }

    // ---- cleanup: per-row head (j<m) and tail (j>=m+4Q), <=5 scalars/row ----
    #pragma unroll
    for (int k = 0; k < 11; ++k) {
        int idx = lane + 32 * k;                          // (row, slot) over 65x5
        int i = idx / 5;
        int s = idx - 5 * i;
        if (i < OUT) {
            int m = (4 - ((i + T) & 3)) & 3;
            int Q = (m < 2) ? 16 : 15;
            if (s < 65 - 4 * Q) {                         // 1 or 5 leftovers
                int j = (s < m) ? s : 4 * Q + s;
                float2 a = ce[i];
                float2 b = ce[j];
                ob[i * OUT + j] = fmaf(a.x, b.x, -a.y * b.y);
            }
        }
    }
}

extern "C" void kernel_launch(void* const* d_in, const int* in_sizes, int n_in,
                              void* d_out, int out_size) {
    const float* x = (const float*)d_in[0];
    float* out = (float*)d_out;
    gasf_kernel<<<N_ROWS / WPB, 32 * WPB>>>(x, out);
}

// round 15
// speedup vs baseline: 1.0339x; 1.0339x over previous
#include <cuda_runtime.h>
#include <cstdint>

#define N_ROWS 2048      // 256 * 8
#define L 128
#define OUT 65
#define OUT2 (OUT * OUT) // 4225
#define THREADS 128
#define EPS 1e-6f

__global__ __launch_bounds__(THREADS) void gasf_kernel(const float* __restrict__ x,
                                                       float* __restrict__ out) {
    __shared__ float2 scss[OUT];                      // (cos, sin)
    __shared__ __align__(16) float sm_tile[OUT2 + 8]; // staged tile, shifted by pad

    const int row = blockIdx.x;
    const int tid = threadIdx.x;
    const int lane = tid & 31;
    const int wid = tid >> 5;           // 0..3
    const float POS_INF = __int_as_float(0x7f800000);

    // ---- preamble: warp 0 computes c,s (proven R7/R10 pattern) ----
    if (wid == 0) {
        float4 v = ((const float4*)(x + row * L))[lane];
        int nib = (v.x != 0.0f ? 1 : 0) | (v.y != 0.0f ? 2 : 0) |
                  (v.z != 0.0f ? 4 : 0) | (v.w != 0.0f ? 8 : 0);
        unsigned m = __ballot_sync(0xffffffffu, nib != 0);

        int first = L, last = -1;
        {
            int lf = __ffs(m) - 1;                 // junk if m==0 (guarded)
            int ll = 31 - __clz(m | 1u);
            int nf = __shfl_sync(0xffffffffu, nib, m ? lf : 0);
            int nl = __shfl_sync(0xffffffffu, nib, m ? ll : 0);
            if (m) {
                first = 4 * lf + (__ffs(nf) - 1);
                last  = 4 * ll + (31 - __clz((unsigned)nl));
            }
        }
        const int p0 = 4 * lane;
        bool val0 = (p0 + 0 >= first) && (p0 + 0 <= last);
        bool val1 = (p0 + 1 >= first) && (p0 + 1 <= last);
        bool val2 = (p0 + 2 >= first) && (p0 + 2 <= last);
        bool val3 = (p0 + 3 >= first) && (p0 + 3 <= last);
        float mn = POS_INF, mx = -POS_INF;
        if (val0) { mn = fminf(mn, v.x); mx = fmaxf(mx, v.x); }
        if (val1) { mn = fminf(mn, v.y); mx = fmaxf(mx, v.y); }
        if (val2) { mn = fminf(mn, v.z); mx = fmaxf(mx, v.z); }
        if (val3) { mn = fminf(mn, v.w); mx = fmaxf(mx, v.w); }
        #pragma unroll
        for (int off = 16; off; off >>= 1) {
            mn = fminf(mn, __shfl_xor_sync(0xffffffffu, mn, off));
            mx = fmaxf(mx, __shfl_xor_sync(0xffffffffu, mx, off));
        }
        float xmin = fminf(mn, 0.0f);          // inf (all-invalid) -> 0, clamp <= 0
        float xmax = fmaxf(mx, 0.0f);
        float inv_range = 2.0f / fmaxf(xmax - xmin, EPS);

        if (p0 < OUT) {
            float vv[4] = { v.x, v.y, v.z, v.w };
            bool vf[4] = { val0, val1, val2, val3 };
            #pragma unroll
            for (int k = 0; k < 4; ++k) {
                int p = p0 + k;
                if (p < OUT) {
                    float xn = vf[k] ? ((vv[k] - xmin) * inv_range - 1.0f) : 0.0f;
                    float c = fminf(fmaxf(xn, -1.0f + EPS), 1.0f - EPS);
                    float s = sqrtf(fmaxf(1.0f - c * c, 0.0f));
                    scss[p] = make_float2(c, s);
                }
            }
        }
    }
    __syncthreads();

    // alignment: (row*4225) % 4 == row % 4 == pad; pad+h in {0,4} => 16B phase match
    const int pad = row & 3;
    const int h = (4 - pad) & 3;               // scalar head elements
    const int t = (OUT2 - h) & 3;              // scalar tail elements
    const int nmid = OUT2 - h - t;             // bulk floats, multiple of 4

    // ---- build tile in smem: conflict-free body, rows split over 4 warps ----
    {
        const float2 b1 = scss[lane];
        const float2 b2 = scss[lane + 32];
        const float2 b3 = scss[64];
        const float nb1y = -b1.y, nb2y = -b2.y, nb3y = -b3.y;
        float* sf = sm_tile + pad;
        #pragma unroll
        for (int i = wid; i < OUT; i += 4) {
            float2 a = scss[i];                // LDS.64 broadcast
            sf[i * OUT + lane]      = fmaf(a.x, b1.x, a.y * nb1y);   // STS stride-1
            sf[i * OUT + lane + 32] = fmaf(a.x, b2.x, a.y * nb2y);
            if (lane == 31)
                sf[i * OUT + 64]    = fmaf(a.x, b3.x, a.y * nb3y);
        }
    }

    // order generic-proxy STS before async-proxy bulk copy, then sync ALL warps
    asm volatile("fence.proxy.async.shared::cta;" ::: "memory");
    __syncthreads();

    // ---- drain: ONE TMA bulk store for the aligned middle ----
    float* orow = out + (size_t)row * OUT2;
    if (tid == 0) {
        unsigned int saddr = (unsigned int)__cvta_generic_to_shared(sm_tile + pad + h);
        asm volatile(
            "cp.async.bulk.global.shared::cta.bulk_group [%0], [%1], %2;"
            :: "l"(orow + h), "r"(saddr), "r"((unsigned int)(nmid * 4))
            : "memory");
        asm volatile("cp.async.bulk.commit_group;" ::: "memory");
    }
    // scalar head + tail (<=6 elements), AFTER the barrier (tile fully built).
    // These only READ sm_tile (concurrent with TMA engine reads — safe).
    if (tid < h) orow[tid] = sm_tile[pad + tid];
    if (tid >= 32 && tid - 32 < t) {
        int e = h + nmid + (tid - 32);
        orow[e] = sm_tile[pad + e];
    }
    if (tid == 0) {
        asm volatile("cp.async.bulk.wait_group.read 0;" ::: "memory");
    }
}

extern "C" void kernel_launch(void* const* d_in, const int* in_sizes, int n_in,
                              void* d_out, int out_size) {
    const float* x = (const float*)d_in[0];
    float* out = (float*)d_out;
    gasf_kernel<<<N_ROWS, THREADS>>>(x, out);
}